// round 5
// baseline (speedup 1.0000x reference)
#include <cuda_runtime.h>
#include <cstddef>

#define BB     32768
#define T_IN   1024
#define STEPS  512
#define NTHR   128
#define NBLK   128                     // 128 blocks * 128 thr * 2 rows = 32768
#define NWARP  (NTHR / 32)
#define OPEN_CH   (T_IN / 32)          // 32
#define CLOSED_CH (STEPS / 32)         // 16
#define TILE_F    (64 * 33)            // one buffer: 64 rows x 33 (padded) floats
#define SMEM_BYTES (NWARP * 2 * TILE_F * 4)

__device__ float g_partial[NBLK];
__device__ unsigned int g_count = 0;

struct W {
    float wii_h, wif_h, wio_h, wig;
    float whi_h, whf_h, who_h, whg;
    float wci_h, wcf_h, wco_h, wcg;
    float bi_h, bf_h, bo_h, bg;
};

__device__ __forceinline__ float htanh(float x) {
    float y;
    asm("tanh.approx.f32 %0, %1;" : "=f"(y) : "f"(x));
    return y;
}
__device__ __forceinline__ float sig_from_half(float a) {
    return fmaf(0.5f, htanh(a), 0.5f);   // sigmoid(2a)
}

__device__ __forceinline__ void step_open(float xv, float& h, float& c, const W& w) {
    float pi = fmaf(xv, w.wii_h, w.bi_h);
    float pf = fmaf(xv, w.wif_h, w.bf_h);
    float po = fmaf(xv, w.wio_h, w.bo_h);
    float pg = fmaf(xv, w.wig,   w.bg);
    float i = sig_from_half(fmaf(h, w.whi_h, pi));
    float f = sig_from_half(fmaf(h, w.whf_h, pf));
    float o = sig_from_half(fmaf(h, w.who_h, po));
    float g = htanh(fmaf(h, w.whg, pg));
    c = fmaf(f, c, i * g);
    h = o * htanh(c);
}
__device__ __forceinline__ void step_closed(float& h, float& c, const W& w) {
    float i = sig_from_half(fmaf(h, w.wci_h, w.bi_h));
    float f = sig_from_half(fmaf(h, w.wcf_h, w.bf_h));
    float o = sig_from_half(fmaf(h, w.wco_h, w.bo_h));
    float g = htanh(fmaf(h, w.wcg, w.bg));
    c = fmaf(f, c, i * g);
    h = o * htanh(c);
}

__device__ __forceinline__ unsigned smem_u32(const void* p) {
    return (unsigned)__cvta_generic_to_shared(p);
}
__device__ __forceinline__ void cpa4(unsigned dst, const float* src) {
    asm volatile("cp.async.ca.shared.global [%0], [%1], 4;" :: "r"(dst), "l"(src));
}
#define CP_COMMIT() asm volatile("cp.async.commit_group;")
#define CP_WAIT1()  asm volatile("cp.async.wait_group 1;")
#define CP_WAIT0()  asm volatile("cp.async.wait_group 0;")

// Issue one 64-row x 32-col chunk: thread `lane` owns column `lane`.
__device__ __forceinline__ void issue_chunk(float (*Tb)[33], const float* srcbase,
                                            size_t stride, int col0, int lane) {
    #pragma unroll
    for (int r = 0; r < 64; r++)
        cpa4(smem_u32(&Tb[r][lane]), srcbase + (size_t)r * stride + col0 + lane);
    CP_COMMIT();
}

extern __shared__ float dsm[];

__global__ __launch_bounds__(NTHR, 1) void lstm_kernel(
    const float* __restrict__ x,   const float* __restrict__ tt,
    const float* __restrict__ h0,  const float* __restrict__ c0,
    const float* __restrict__ w_ih, const float* __restrict__ w_hh,
    const float* __restrict__ b_ih, const float* __restrict__ b_hh,
    float* __restrict__ pred, float* __restrict__ loss_out)
{
    const int tid  = threadIdx.x;
    const int lane = tid & 31;
    const int wid  = tid >> 5;
    const int rb   = blockIdx.x * (NTHR * 2) + wid * 64;   // warp's first row
    const int bA   = rb + lane;
    const int bB   = rb + 32 + lane;

    float* Twarp = dsm + wid * (2 * TILE_F);
    float (*T0)[33] = (float(*)[33])(Twarp);
    float (*T1)[33] = (float(*)[33])(Twarp + TILE_F);

    const float* xw = x  + (size_t)rb * T_IN;
    const float* tw = tt + (size_t)rb * STEPS;
    float* pw = pred ? (pred + (size_t)rb * STEPS) : nullptr;

    // prologue: x chunk 0 -> buf0
    issue_chunk(T0, xw, T_IN, 0, lane);

    W w;
    {
        float wi0 = w_ih[0], wi1 = w_ih[1], wi2 = w_ih[2], wi3 = w_ih[3];
        float wh0 = w_hh[0], wh1 = w_hh[1], wh2 = w_hh[2], wh3 = w_hh[3];
        float b0 = b_ih[0] + b_hh[0];
        float b1 = b_ih[1] + b_hh[1];
        float b2 = b_ih[2] + b_hh[2];
        float b3 = b_ih[3] + b_hh[3];
        // gate order: i, f, g, o
        w.wii_h = 0.5f * wi0; w.whi_h = 0.5f * wh0; w.bi_h = 0.5f * b0;
        w.wif_h = 0.5f * wi1; w.whf_h = 0.5f * wh1; w.bf_h = 0.5f * b1;
        w.wig   = wi2;        w.whg   = wh2;        w.bg   = b2;
        w.wio_h = 0.5f * wi3; w.who_h = 0.5f * wh3; w.bo_h = 0.5f * b3;
        w.wci_h = w.wii_h + w.whi_h;
        w.wcf_h = w.wif_h + w.whf_h;
        w.wcg   = w.wig   + w.whg;
        w.wco_h = w.wio_h + w.who_h;
    }

    float hA = h0[bA], cA = c0[bA];
    float hB = h0[bB], cB = c0[bB];

    // ---------------- open loop: 1024 steps, 2 rows/thread --------------------
    #pragma unroll 1
    for (int ch = 0; ch < OPEN_CH; ch++) {
        float (*Tb)[33] = (ch & 1) ? T1 : T0;
        float (*Tn)[33] = (ch & 1) ? T0 : T1;
        if (ch < OPEN_CH - 1) issue_chunk(Tn, xw, T_IN, (ch + 1) * 32, lane);
        else                  issue_chunk(Tn, tw, STEPS, 0, lane);
        CP_WAIT1();
        __syncwarp();
        #pragma unroll
        for (int k = 0; k < 32; k++) {
            float xA = Tb[lane][k];
            float xB = Tb[32 + lane][k];
            step_open(xA, hA, cA, w);
            step_open(xB, hB, cB, w);
        }
    }
    // x[:, -1] lives in the last open buffer (buf 1), col 31
    const float xlA = T1[lane][31];
    const float xlB = T1[32 + lane][31];

    // ---------------- closed loop: 512 steps -----------------------------------
    float lacc = 0.0f;

    #pragma unroll 1
    for (int ch = 0; ch < CLOSED_CH; ch++) {
        float (*Tb)[33] = (ch & 1) ? T1 : T0;
        float (*Tn)[33] = (ch & 1) ? T0 : T1;
        if (ch < CLOSED_CH - 1) {
            issue_chunk(Tn, tw, STEPS, (ch + 1) * 32, lane);
            CP_WAIT1();
        } else {
            CP_WAIT0();
        }
        __syncwarp();

        #pragma unroll
        for (int k = 0; k < 32; k++) {
            if (ch == 0 && k == 0) {
                step_open(xlA, hA, cA, w);     // step 0 consumes x[:, -1]
                step_open(xlB, hB, cB, w);
            } else {
                step_closed(hA, cA, w);
                step_closed(hB, cB, w);
            }
            float tA = Tb[lane][k],      tB = Tb[32 + lane][k];
            float dA = hA - tA,          dB = hB - tB;
            lacc = fmaf(dA, dA, lacc);
            lacc = fmaf(dB, dB, lacc);
            Tb[lane][k] = hA;
            Tb[32 + lane][k] = hB;
        }
        __syncwarp();
        if (pw) {
            const int s0 = ch * 32;
            #pragma unroll
            for (int r = 0; r < 64; r++)
                __stcs(pw + (size_t)r * STEPS + s0 + lane, Tb[r][lane]);
        }
    }

    // ---------------- deterministic in-kernel loss reduction -------------------
    #pragma unroll
    for (int off = 16; off; off >>= 1)
        lacc += __shfl_xor_sync(0xffffffffu, lacc, off);

    __shared__ float ss[NWARP];
    if (lane == 0) ss[wid] = lacc;
    __syncthreads();

    __shared__ bool is_last;
    if (tid == 0) {
        float s2 = 0.0f;
        #pragma unroll
        for (int i = 0; i < NWARP; i++) s2 += ss[i];
        g_partial[blockIdx.x] = s2;
        __threadfence();
        unsigned int ticket = atomicAdd(&g_count, 1u);
        is_last = (ticket == NBLK - 1);
    }
    __syncthreads();

    if (is_last) {
        if (loss_out) {
            __shared__ float red[NBLK];
            red[tid] = g_partial[tid];
            __syncthreads();
            #pragma unroll
            for (int stride = NBLK / 2; stride > 0; stride >>= 1) {
                if (tid < stride) red[tid] += red[tid + stride];
                __syncthreads();
            }
            if (tid == 0) {
                *loss_out = red[0] / (float)BB;
                g_count = 0;
            }
        } else if (tid == 0) {
            g_count = 0;
        }
    }
}

extern "C" void kernel_launch(void* const* d_in, const int* in_sizes, int n_in,
                              void* d_out, int out_size) {
    const float* x    = (const float*)d_in[0];
    const float* t    = (const float*)d_in[1];
    const float* h0   = (const float*)d_in[2];
    const float* c0   = (const float*)d_in[3];
    const float* w_ih = (const float*)d_in[4];
    const float* w_hh = (const float*)d_in[5];
    const float* b_ih = (const float*)d_in[6];
    const float* b_hh = (const float*)d_in[7];

    float* out = (float*)d_out;
    const long long total = (long long)BB * STEPS;

    float* loss_out = nullptr;
    float* pred_out = nullptr;
    if ((long long)out_size == total + 1) {
        loss_out = out;
        pred_out = out + 1;
    } else if ((long long)out_size == total) {
        pred_out = out;
    } else if (out_size == 1) {
        loss_out = out;
    } else {
        loss_out = out;
        if (out_size > 1) pred_out = out + 1;
    }

    cudaFuncSetAttribute(lstm_kernel,
                         cudaFuncAttributeMaxDynamicSharedMemorySize, SMEM_BYTES);

    lstm_kernel<<<NBLK, NTHR, SMEM_BYTES>>>(x, t, h0, c0, w_ih, w_hh, b_ih, b_hh,
                                            pred_out, loss_out);
}

// round 6
// speedup vs baseline: 1.2515x; 1.2515x over previous
#include <cuda_runtime.h>
#include <cuda_fp16.h>
#include <cstddef>

#define BB     32768
#define T_IN   1024
#define STEPS  512
#define NTHR   256
#define NBLK   (BB / NTHR)          // 128 blocks -> 8 warps on each of 128 SMs
#define NWARP  (NTHR / 32)

__device__ float g_partial[NBLK];
__device__ unsigned int g_count = 0;

struct W {
    float wii_h, wif_h, wio_h, wig;      // w_ih (i,f,o half-scaled; g full)
    float whi_h, whf_h, who_h, whg;      // w_hh
    float wci_h, wcf_h, wco_h, wcg;      // combined wi+wh (closed loop)
    float bi_h, bf_h, bo_h, bg;          // biases
};

__device__ __forceinline__ float htanh(float x) {
    float y;
    asm("tanh.approx.f32 %0, %1;" : "=f"(y) : "f"(x));
    return y;
}
__device__ __forceinline__ float sig_from_half(float a) {
    // sigmoid(2a) = 0.5 + 0.5*tanh(a)
    return fmaf(0.5f, htanh(a), 0.5f);
}

// Two sigmoids with ONE MUFU: sigmoid(2a), sigmoid(2b) via tanh.approx.f16x2.
__device__ __forceinline__ float2 sig2(float a, float b) {
    __half2 hin = __floats2half2_rn(a, b);
    unsigned u = *reinterpret_cast<unsigned*>(&hin);
    unsigned r;
    asm("tanh.approx.f16x2 %0, %1;" : "=r"(r) : "r"(u));
    __half2 t = *reinterpret_cast<__half2*>(&r);
    const __half2 half05 = __floats2half2_rn(0.5f, 0.5f);
    __half2 s = __hfma2(t, half05, half05);
    return make_float2(__low2float(s), __high2float(s));
}

__device__ __forceinline__ void step_open(float xv, float& h, float& c, const W& w) {
    float pi = fmaf(xv, w.wii_h, w.bi_h);
    float pf = fmaf(xv, w.wif_h, w.bf_h);
    float po = fmaf(xv, w.wio_h, w.bo_h);
    float pg = fmaf(xv, w.wig,   w.bg);
    float2 sif = sig2(fmaf(h, w.whi_h, pi), fmaf(h, w.whf_h, pf));
    float i = sif.x, f = sif.y;
    float o = sig_from_half(fmaf(h, w.who_h, po));
    float g = htanh(fmaf(h, w.whg, pg));
    c = fmaf(f, c, i * g);
    h = o * htanh(c);
}

__device__ __forceinline__ void step_closed(float& h, float& c, const W& w) {
    float2 sif = sig2(fmaf(h, w.wci_h, w.bi_h), fmaf(h, w.wcf_h, w.bf_h));
    float i = sif.x, f = sif.y;
    float o = sig_from_half(fmaf(h, w.wco_h, w.bo_h));
    float g = htanh(fmaf(h, w.wcg, w.bg));
    c = fmaf(f, c, i * g);
    h = o * htanh(c);
}

__global__ __launch_bounds__(NTHR, 1) void lstm_kernel(
    const float* __restrict__ x,   const float* __restrict__ tt,
    const float* __restrict__ h0,  const float* __restrict__ c0,
    const float* __restrict__ w_ih, const float* __restrict__ w_hh,
    const float* __restrict__ b_ih, const float* __restrict__ b_hh,
    float* __restrict__ pred, float* __restrict__ loss_out)
{
    const int tid  = threadIdx.x;
    const int lane = tid & 31;
    const int wid  = tid >> 5;
    const int b    = blockIdx.x * NTHR + tid;
    const int wb   = blockIdx.x * NTHR + (wid << 5);   // warp's base batch row

    // per-warp transpose tile: [row=batch-lane][col=step], +1 pad -> conflict-free
    __shared__ float tile[NWARP][32][33];
    float (*T)[33] = tile[wid];

    W w;
    {
        float wi0 = w_ih[0], wi1 = w_ih[1], wi2 = w_ih[2], wi3 = w_ih[3];
        float wh0 = w_hh[0], wh1 = w_hh[1], wh2 = w_hh[2], wh3 = w_hh[3];
        float b0 = b_ih[0] + b_hh[0];
        float b1 = b_ih[1] + b_hh[1];
        float b2 = b_ih[2] + b_hh[2];
        float b3 = b_ih[3] + b_hh[3];
        // gate order: i, f, g, o
        w.wii_h = 0.5f * wi0; w.whi_h = 0.5f * wh0; w.bi_h = 0.5f * b0;
        w.wif_h = 0.5f * wi1; w.whf_h = 0.5f * wh1; w.bf_h = 0.5f * b1;
        w.wig   = wi2;        w.whg   = wh2;        w.bg   = b2;
        w.wio_h = 0.5f * wi3; w.who_h = 0.5f * wh3; w.bo_h = 0.5f * b3;
        w.wci_h = w.wii_h + w.whi_h;
        w.wcf_h = w.wif_h + w.whf_h;
        w.wcg   = w.wig   + w.whg;
        w.wco_h = w.wio_h + w.who_h;
    }

    float h = h0[b];
    float c = c0[b];

    const float* xw = x + (size_t)wb * T_IN;
    const float* tw = tt + (size_t)wb * STEPS;
    float* pw = pred ? (pred + (size_t)wb * STEPS) : nullptr;

    // prefetch registers: p[r] = element (row wb+r, col chunk*32+lane)
    float p[32];

    // ---------------- open loop: 1024 steps, register-prefetched chunks -------
    #pragma unroll
    for (int r = 0; r < 32; r++)
        p[r] = __ldcs(xw + (size_t)r * T_IN + lane);

    #pragma unroll 1
    for (int ch = 0; ch < T_IN / 32; ch++) {
        __syncwarp();
        #pragma unroll
        for (int r = 0; r < 32; r++)
            T[r][lane] = p[r];
        __syncwarp();

        if (ch < T_IN / 32 - 1) {
            const float* src = xw + (size_t)(ch + 1) * 32;
            #pragma unroll
            for (int r = 0; r < 32; r++)
                p[r] = __ldcs(src + (size_t)r * T_IN + lane);
        } else {
            // last open chunk: prefetch first closed-loop target chunk
            #pragma unroll
            for (int r = 0; r < 32; r++)
                p[r] = __ldcs(tw + (size_t)r * STEPS + lane);
        }

        #pragma unroll
        for (int k = 0; k < 32; k++)
            step_open(T[lane][k], h, c, w);
    }
    const float xlast = T[lane][31];                 // x[b, T_IN-1]

    // ---------------- closed loop: 512 steps, prefetch + coalesced pred -------
    float lacc = 0.0f;

    #pragma unroll 1
    for (int ch = 0; ch < STEPS / 32; ch++) {
        const int s0 = ch * 32;
        __syncwarp();
        #pragma unroll
        for (int r = 0; r < 32; r++)
            T[r][lane] = p[r];
        __syncwarp();

        if (ch < STEPS / 32 - 1) {
            const float* src = tw + (size_t)(ch + 1) * 32;
            #pragma unroll
            for (int r = 0; r < 32; r++)
                p[r] = __ldcs(src + (size_t)r * STEPS + lane);
        }

        if (ch == 0) {
            step_open(xlast, h, c, w);               // step 0 uses x[:, -1]
            { float tv = T[lane][0]; float d = h - tv; lacc = fmaf(d, d, lacc); T[lane][0] = h; }
            #pragma unroll
            for (int k = 1; k < 32; k++) {
                step_closed(h, c, w);
                float tv = T[lane][k]; float d = h - tv; lacc = fmaf(d, d, lacc); T[lane][k] = h;
            }
        } else {
            #pragma unroll
            for (int k = 0; k < 32; k++) {
                step_closed(h, c, w);
                float tv = T[lane][k]; float d = h - tv; lacc = fmaf(d, d, lacc); T[lane][k] = h;
            }
        }
        __syncwarp();
        if (pw) {
            #pragma unroll
            for (int r = 0; r < 32; r++)             // coalesced pred stores
                __stcs(pw + (size_t)r * STEPS + s0 + lane, T[r][lane]);
        }
    }

    // ---------------- deterministic in-kernel loss reduction ------------------
    #pragma unroll
    for (int off = 16; off; off >>= 1)
        lacc += __shfl_xor_sync(0xffffffffu, lacc, off);

    __shared__ float ss[NWARP];
    if (lane == 0) ss[wid] = lacc;
    __syncthreads();

    __shared__ bool is_last;
    if (tid == 0) {
        float s2 = 0.0f;
        #pragma unroll
        for (int i = 0; i < NWARP; i++) s2 += ss[i];
        g_partial[blockIdx.x] = s2;
        __threadfence();
        unsigned int ticket = atomicAdd(&g_count, 1u);
        is_last = (ticket == NBLK - 1);
    }
    __syncthreads();

    if (is_last) {
        if (loss_out) {
            __shared__ float red[NBLK];
            if (tid < NBLK) red[tid] = g_partial[tid];
            __syncthreads();
            #pragma unroll
            for (int stride = NBLK / 2; stride > 0; stride >>= 1) {
                if (tid < stride) red[tid] += red[tid + stride];
                __syncthreads();
            }
            if (tid == 0) {
                *loss_out = red[0] / (float)BB;
                g_count = 0;
            }
        } else if (tid == 0) {
            g_count = 0;
        }
    }
}

extern "C" void kernel_launch(void* const* d_in, const int* in_sizes, int n_in,
                              void* d_out, int out_size) {
    const float* x    = (const float*)d_in[0];
    const float* t    = (const float*)d_in[1];
    const float* h0   = (const float*)d_in[2];
    const float* c0   = (const float*)d_in[3];
    const float* w_ih = (const float*)d_in[4];
    const float* w_hh = (const float*)d_in[5];
    const float* b_ih = (const float*)d_in[6];
    const float* b_hh = (const float*)d_in[7];

    float* out = (float*)d_out;
    const long long total = (long long)BB * STEPS;

    float* loss_out = nullptr;
    float* pred_out = nullptr;
    if ((long long)out_size == total + 1) {
        loss_out = out;
        pred_out = out + 1;
    } else if ((long long)out_size == total) {
        pred_out = out;
    } else if (out_size == 1) {
        loss_out = out;
    } else {
        loss_out = out;
        if (out_size > 1) pred_out = out + 1;
    }

    lstm_kernel<<<NBLK, NTHR>>>(x, t, h0, c0, w_ih, w_hh, b_ih, b_hh,
                                pred_out, loss_out);
}

// round 7
// speedup vs baseline: 1.2585x; 1.0056x over previous
#include <cuda_runtime.h>
#include <cuda_fp16.h>
#include <cstddef>

#define BB     32768
#define T_IN   1024
#define STEPS  512
#define NTHR   256
#define NBLK   (BB / NTHR)          // 128 blocks -> 8 warps on each of 128 SMs
#define NWARP  (NTHR / 32)

__device__ float g_partial[NBLK];
__device__ unsigned int g_count = 0;

struct W {
    float wii_h, wif_h, wio_h, wig;      // w_ih (i,f,o half-scaled; g full)
    float whi_h, whf_h, who_h, whg;      // w_hh
    float wci_h, wcf_h, wco_h, wcg;      // combined wi+wh (closed loop)
    float bi_h, bf_h, bo_h, bg;          // biases
};

__device__ __forceinline__ float htanh(float x) {
    float y;
    asm("tanh.approx.f32 %0, %1;" : "=f"(y) : "f"(x));
    return y;
}
__device__ __forceinline__ float sig_from_half(float a) {
    // sigmoid(2a) = 0.5 + 0.5*tanh(a)
    return fmaf(0.5f, htanh(a), 0.5f);
}

// Two sigmoids with ONE MUFU: sigmoid(2a), sigmoid(2b) via tanh.approx.f16x2.
__device__ __forceinline__ float2 sig2(float a, float b) {
    __half2 hin = __floats2half2_rn(a, b);
    unsigned u = *reinterpret_cast<unsigned*>(&hin);
    unsigned r;
    asm("tanh.approx.f16x2 %0, %1;" : "=r"(r) : "r"(u));
    __half2 t = *reinterpret_cast<__half2*>(&r);
    const __half2 half05 = __floats2half2_rn(0.5f, 0.5f);
    __half2 s = __hfma2(t, half05, half05);
    return make_float2(__low2float(s), __high2float(s));
}

__device__ __forceinline__ void step_open(float xv, float& h, float& c, const W& w) {
    float pi = fmaf(xv, w.wii_h, w.bi_h);
    float pf = fmaf(xv, w.wif_h, w.bf_h);
    float po = fmaf(xv, w.wio_h, w.bo_h);
    float pg = fmaf(xv, w.wig,   w.bg);
    float2 sif = sig2(fmaf(h, w.whi_h, pi), fmaf(h, w.whf_h, pf));
    float i = sif.x, f = sif.y;
    float o = sig_from_half(fmaf(h, w.who_h, po));
    float g = htanh(fmaf(h, w.whg, pg));
    c = fmaf(f, c, i * g);
    h = o * htanh(c);
}

__device__ __forceinline__ void step_closed(float& h, float& c, const W& w) {
    float2 sif = sig2(fmaf(h, w.wci_h, w.bi_h), fmaf(h, w.wcf_h, w.bf_h));
    float i = sif.x, f = sif.y;
    float o = sig_from_half(fmaf(h, w.wco_h, w.bo_h));
    float g = htanh(fmaf(h, w.wcg, w.bg));
    c = fmaf(f, c, i * g);
    h = o * htanh(c);
}

__global__ __launch_bounds__(NTHR, 1) void lstm_kernel(
    const float* __restrict__ x,   const float* __restrict__ tt,
    const float* __restrict__ h0,  const float* __restrict__ c0,
    const float* __restrict__ w_ih, const float* __restrict__ w_hh,
    const float* __restrict__ b_ih, const float* __restrict__ b_hh,
    float* __restrict__ pred, float* __restrict__ loss_out)
{
    const int tid  = threadIdx.x;
    const int lane = tid & 31;
    const int wid  = tid >> 5;
    const int b    = blockIdx.x * NTHR + tid;
    const int wb   = blockIdx.x * NTHR + (wid << 5);   // warp's base batch row

    // per-warp transpose tile: [row=batch-lane][col=step], +1 pad -> conflict-free
    __shared__ float tile[NWARP][32][33];
    float (*T)[33] = tile[wid];

    W w;
    {
        float wi0 = w_ih[0], wi1 = w_ih[1], wi2 = w_ih[2], wi3 = w_ih[3];
        float wh0 = w_hh[0], wh1 = w_hh[1], wh2 = w_hh[2], wh3 = w_hh[3];
        float b0 = b_ih[0] + b_hh[0];
        float b1 = b_ih[1] + b_hh[1];
        float b2 = b_ih[2] + b_hh[2];
        float b3 = b_ih[3] + b_hh[3];
        // gate order: i, f, g, o
        w.wii_h = 0.5f * wi0; w.whi_h = 0.5f * wh0; w.bi_h = 0.5f * b0;
        w.wif_h = 0.5f * wi1; w.whf_h = 0.5f * wh1; w.bf_h = 0.5f * b1;
        w.wig   = wi2;        w.whg   = wh2;        w.bg   = b2;
        w.wio_h = 0.5f * wi3; w.who_h = 0.5f * wh3; w.bo_h = 0.5f * b3;
        w.wci_h = w.wii_h + w.whi_h;
        w.wcf_h = w.wif_h + w.whf_h;
        w.wcg   = w.wig   + w.whg;
        w.wco_h = w.wio_h + w.who_h;
    }

    float h = h0[b];
    float c = c0[b];

    const float* xw = x + (size_t)wb * T_IN;
    const float* tw = tt + (size_t)wb * STEPS;
    float* pw = pred ? (pred + (size_t)wb * STEPS) : nullptr;

    // prefetch registers: p[r] = element (row wb+r, col chunk*32+lane)
    float p[32];

    // ---------------- open loop: 1024 steps, register-prefetched chunks -------
    #pragma unroll
    for (int r = 0; r < 32; r++)
        p[r] = __ldcs(xw + (size_t)r * T_IN + lane);

    #pragma unroll 1
    for (int ch = 0; ch < T_IN / 32; ch++) {
        __syncwarp();
        #pragma unroll
        for (int r = 0; r < 32; r++)
            T[r][lane] = p[r];
        __syncwarp();

        if (ch < T_IN / 32 - 1) {
            const float* src = xw + (size_t)(ch + 1) * 32;
            #pragma unroll
            for (int r = 0; r < 32; r++)
                p[r] = __ldcs(src + (size_t)r * T_IN + lane);
        } else {
            // last open chunk: prefetch first closed-loop target chunk
            #pragma unroll
            for (int r = 0; r < 32; r++)
                p[r] = __ldcs(tw + (size_t)r * STEPS + lane);
        }

        #pragma unroll
        for (int k = 0; k < 32; k++)
            step_open(T[lane][k], h, c, w);
    }
    const float xlast = T[lane][31];                 // x[b, T_IN-1]

    // ---------------- closed loop: 512 steps, prefetch + coalesced pred -------
    float lacc = 0.0f;

    #pragma unroll 1
    for (int ch = 0; ch < STEPS / 32; ch++) {
        const int s0 = ch * 32;
        __syncwarp();
        #pragma unroll
        for (int r = 0; r < 32; r++)
            T[r][lane] = p[r];
        __syncwarp();

        if (ch < STEPS / 32 - 1) {
            const float* src = tw + (size_t)(ch + 1) * 32;
            #pragma unroll
            for (int r = 0; r < 32; r++)
                p[r] = __ldcs(src + (size_t)r * STEPS + lane);
        }

        if (ch == 0) {
            step_open(xlast, h, c, w);               // step 0 uses x[:, -1]
            { float tv = T[lane][0]; float d = h - tv; lacc = fmaf(d, d, lacc); T[lane][0] = h; }
            #pragma unroll
            for (int k = 1; k < 32; k++) {
                step_closed(h, c, w);
                float tv = T[lane][k]; float d = h - tv; lacc = fmaf(d, d, lacc); T[lane][k] = h;
            }
        } else {
            #pragma unroll
            for (int k = 0; k < 32; k++) {
                step_closed(h, c, w);
                float tv = T[lane][k]; float d = h - tv; lacc = fmaf(d, d, lacc); T[lane][k] = h;
            }
        }
        __syncwarp();
        if (pw) {
            #pragma unroll
            for (int r = 0; r < 32; r++)             // coalesced pred stores
                __stcs(pw + (size_t)r * STEPS + s0 + lane, T[r][lane]);
        }
    }

    // ---------------- deterministic in-kernel loss reduction ------------------
    #pragma unroll
    for (int off = 16; off; off >>= 1)
        lacc += __shfl_xor_sync(0xffffffffu, lacc, off);

    __shared__ float ss[NWARP];
    if (lane == 0) ss[wid] = lacc;
    __syncthreads();

    __shared__ bool is_last;
    if (tid == 0) {
        float s2 = 0.0f;
        #pragma unroll
        for (int i = 0; i < NWARP; i++) s2 += ss[i];
        g_partial[blockIdx.x] = s2;
        __threadfence();
        unsigned int ticket = atomicAdd(&g_count, 1u);
        is_last = (ticket == NBLK - 1);
    }
    __syncthreads();

    if (is_last) {
        if (loss_out) {
            __shared__ float red[NBLK];
            if (tid < NBLK) red[tid] = g_partial[tid];
            __syncthreads();
            #pragma unroll
            for (int stride = NBLK / 2; stride > 0; stride >>= 1) {
                if (tid < stride) red[tid] += red[tid + stride];
                __syncthreads();
            }
            if (tid == 0) {
                *loss_out = red[0] / (float)BB;
                g_count = 0;
            }
        } else if (tid == 0) {
            g_count = 0;
        }
    }
}

extern "C" void kernel_launch(void* const* d_in, const int* in_sizes, int n_in,
                              void* d_out, int out_size) {
    const float* x    = (const float*)d_in[0];
    const float* t    = (const float*)d_in[1];
    const float* h0   = (const float*)d_in[2];
    const float* c0   = (const float*)d_in[3];
    const float* w_ih = (const float*)d_in[4];
    const float* w_hh = (const float*)d_in[5];
    const float* b_ih = (const float*)d_in[6];
    const float* b_hh = (const float*)d_in[7];

    float* out = (float*)d_out;
    const long long total = (long long)BB * STEPS;

    float* loss_out = nullptr;
    float* pred_out = nullptr;
    if ((long long)out_size == total + 1) {
        loss_out = out;
        pred_out = out + 1;
    } else if ((long long)out_size == total) {
        pred_out = out;
    } else if (out_size == 1) {
        loss_out = out;
    } else {
        loss_out = out;
        if (out_size > 1) pred_out = out + 1;
    }

    lstm_kernel<<<NBLK, NTHR>>>(x, t, h0, c0, w_ih, w_hh, b_ih, b_hh,
                                pred_out, loss_out);
}